// round 15
// baseline (speedup 1.0000x reference)
#include <cuda_runtime.h>

#define BATCH 128
#define SITES 256
#define BOND 64
#define NOUT 10
#define HALFS 128            // sites per half
#define NPAIRS 64            // site pairs per half
#define SITE_BYTES 32768     // 64*64*2 floats
#define PAIR_BYTES 65536     // 2 sites per TMA stage
#define STAGES 3             // 3 * 64KB ring = 192KB

typedef unsigned long long ull;

// Scratch (device globals — no allocation allowed)
__device__ __align__(16) float g_ct[HALFS * BOND * BOND * 2]; // right half, transposed+reversed
__device__ float g_vL[BATCH * BOND];
__device__ float g_wR[BATCH * BOND];

// ---- packed f32x2 helpers ----
static __device__ __forceinline__ ull ffma2(ull a, ull b, ull c) {
    ull d;
    asm("fma.rn.f32x2 %0, %1, %2, %3;" : "=l"(d) : "l"(a), "l"(b), "l"(c));
    return d;
}
static __device__ __forceinline__ ull fadd2(ull a, ull b) {
    ull d;
    asm("add.rn.f32x2 %0, %1, %2;" : "=l"(d) : "l"(a), "l"(b));
    return d;
}
static __device__ __forceinline__ float f2lo(ull v) {
    return __uint_as_float((unsigned)(v & 0xffffffffull));
}
static __device__ __forceinline__ float f2hi(ull v) {
    return __uint_as_float((unsigned)(v >> 32));
}
static __device__ __forceinline__ ull dup2(float v) {
    unsigned u = __float_as_uint(v);
    return ((ull)u << 32) | u;
}
static __device__ __forceinline__ unsigned smem_u32(const void* p) {
    return (unsigned)__cvta_generic_to_shared(p);
}

// ---- mbarrier / bulk-copy primitives ----
static __device__ __forceinline__ void mbar_init(unsigned addr, unsigned count) {
    asm volatile("mbarrier.init.shared.b64 [%0], %1;" :: "r"(addr), "r"(count) : "memory");
}
static __device__ __forceinline__ void mbar_expect_tx(unsigned addr, unsigned bytes) {
    asm volatile("mbarrier.arrive.expect_tx.shared.b64 _, [%0], %1;"
                 :: "r"(addr), "r"(bytes) : "memory");
}
static __device__ __forceinline__ void mbar_arrive(unsigned addr) {
    asm volatile("mbarrier.arrive.shared.b64 _, [%0];" :: "r"(addr) : "memory");
}
static __device__ __forceinline__ void mbar_wait(unsigned addr, unsigned parity) {
    asm volatile(
        "{\n\t"
        ".reg .pred P;\n\t"
        "WAIT_%=:\n\t"
        "mbarrier.try_wait.parity.acquire.cta.shared::cta.b64 P, [%0], %1, 0x989680;\n\t"
        "@P bra.uni DONE_%=;\n\t"
        "bra.uni WAIT_%=;\n\t"
        "DONE_%=:\n\t"
        "}"
        :: "r"(addr), "r"(parity) : "memory");
}
static __device__ __forceinline__ void bulk_g2s(unsigned dst, const void* src,
                                                unsigned bytes, unsigned mbar) {
    asm volatile(
        "cp.async.bulk.shared::cluster.global.mbarrier::complete_tx::bytes [%0], [%1], %2, [%3];"
        :: "r"(dst), "l"(src), "r"(bytes), "r"(mbar) : "memory");
}

// ============================================================
// Kernel 0: no-op — keeps ncu's -s 5 capture window on chain_kernel.
// ============================================================
__global__ void dummy_kernel() {}

// ============================================================
// Kernel 1: repack right-half cores only.
// g_ct[t][r][2l+i] = cores[255 - t][l][r][i]  (transpose, reverse order)
// ============================================================
__global__ void __launch_bounds__(256) repack_kernel(const float* __restrict__ cores) {
    int t = blockIdx.x;            // 0..127
    int s = 255 - t;
    __shared__ float2 sh[64 * 65];
    const float2* src = (const float2*)cores + (size_t)s * 4096; // [l*64 + r] -> (c0,c1)
    float2* dst = (float2*)g_ct + (size_t)t * 4096;              // [r*64 + l]
    for (int idx = threadIdx.x; idx < 4096; idx += blockDim.x) {
        int l = idx >> 6, r = idx & 63;
        sh[r * 65 + l] = src[idx];
    }
    __syncthreads();
    for (int idx = threadIdx.x; idx < 4096; idx += blockDim.x) {
        int r = idx >> 6, l = idx & 63;
        dst[idx] = sh[r * 65 + l];
    }
}

// ============================================================
// Kernel 2: vector chains. grid (64,2) x 64 threads = 128 blocks.
// Warp 0 (consumer): BOTH chains of the block (8 accumulators, tile
// read once), inner loop with EXPLICIT depth-2 register prefetch so
// the 29-cyc LDS latency is overlapped by FFMA issue instead of
// being exposed every iteration (the R13 diagnosis).
// Warp 1 lane 0 (producer): dedicated TMA loop over all 64 pairs
// (wait-empty -> expect -> bulk), so the consumer's serial path has
// only the full-wait fast path.
//   full[stg]  (count 1): TMA complete_tx; consumer parity-waits.
//   empty[stg] (count 1): consumer releases once per pair.
// ============================================================
__global__ void __launch_bounds__(64) chain_kernel(
    const float* __restrict__ x,      // [B][S][2]
    const float* __restrict__ cores,  // [S][l][r][2]
    const float* __restrict__ lvec,
    const float* __restrict__ rvec)
{
    extern __shared__ __align__(128) char dynsmem[];   // STAGES * 64KB
    __shared__ __align__(16) ull st[2][2][64];         // [buf][chain][j] = (v,v)
    __shared__ __align__(16) float2 sx[2][HALFS];      // per-chain x, site order
    __shared__ __align__(8) ull full_store[STAGES];
    __shared__ __align__(8) ull empty_store[STAGES];

    const int tid  = threadIdx.x;
    const int w    = tid >> 5;
    const int lane = tid & 31;
    const int half = blockIdx.y;
    const int o0   = 2 * lane;

    unsigned fmb[STAGES], emb[STAGES];
    #pragma unroll
    for (int si = 0; si < STAGES; ++si) {
        fmb[si] = smem_u32(&full_store[si]);
        emb[si] = smem_u32(&empty_store[si]);
    }
    if (tid == 0) {
        #pragma unroll
        for (int si = 0; si < STAGES; ++si) {
            mbar_init(fmb[si], 1);
            mbar_init(emb[si], 1);
        }
    }

    // Stage per-chain x values (site order t).
    for (int i = tid; i < 2 * HALFS; i += 64) {
        int c = i >> 7, t = i & 127;
        int batch = blockIdx.x * 2 + c;
        int s = half ? (255 - t) : t;
        sx[c][t] = *(const float2*)(x + ((size_t)batch * SITES + s) * 2);
    }
    // Init state buffer 0 with the boundary vector (consumer warp).
    const float* bv = half ? rvec : lvec;
    float rA0, rA1, rB0, rB1;
    if (w == 0) {
        rA0 = bv[o0]; rA1 = bv[o0 + 1];
        rB0 = rA0;    rB1 = rA1;
        st[0][0][o0] = dup2(rA0); st[0][0][o0 + 1] = dup2(rA1);
        st[0][1][o0] = dup2(rB0); st[0][1][o0 + 1] = dup2(rB1);
    }
    __syncthreads();  // mbar init + state/x visible

    const char* gsrc = half ? (const char*)g_ct : (const char*)cores;

    if (w == 1) {
        // ---------------- Producer warp ----------------
        if (lane == 0) {
            for (int pr = 0; pr < NPAIRS; ++pr) {
                const int stg = pr % STAGES;
                const int lap = pr / STAGES;
                if (lap >= 1)
                    mbar_wait(emb[stg], (lap - 1) & 1);  // consumer freed previous use
                mbar_expect_tx(fmb[stg], PAIR_BYTES);
                bulk_g2s(smem_u32(dynsmem + (size_t)stg * PAIR_BYTES),
                         gsrc + (size_t)pr * PAIR_BYTES, PAIR_BYTES, fmb[stg]);
            }
        }
        return;
    }

    // ---------------- Consumer warp (both chains) ----------------
    for (int t = 0; t < HALFS; ++t) {
        const int pair = t >> 1;
        const int stg  = pair % STAGES;
        if ((t & 1) == 0)
            mbar_wait(fmb[stg], (pair / STAGES) & 1);

        const int cur = t & 1;  // state read buffer; write buffer = cur^1
        const ulonglong2* tp =
            (const ulonglong2*)(dynsmem + (size_t)stg * PAIR_BYTES + (size_t)cur * SITE_BYTES)
            + lane;
        const ulonglong2* sA = (const ulonglong2*)&st[cur][0][0];
        const ulonglong2* sB = (const ulonglong2*)&st[cur][1][0];

        // Depth-2 software pipeline: iteration jj consumes values loaded
        // two iterations earlier; loads for jj+2 issue before jj's FMAs.
        ull a0 = 0, a1 = 0, a2 = 0, a3 = 0;   // chain A
        ull b0 = 0, b1 = 0, b2 = 0, b3 = 0;   // chain B

        ulonglong2 ca0 = tp[0],   cb0 = tp[32], vA0 = sA[0], vB0 = sB[0];
        ulonglong2 ca1 = tp[64],  cb1 = tp[96], vA1 = sA[1], vB1 = sB[1];

        #pragma unroll
        for (int jj = 0; jj < 32; ++jj) {
            ulonglong2 can, cbn, vAn, vBn;
            if (jj < 30) {
                can = tp[(2 * jj + 4) * 32];
                cbn = tp[(2 * jj + 5) * 32];
                vAn = sA[jj + 2];
                vBn = sB[jj + 2];
            }
            a0 = ffma2(ca0.x, vA0.x, a0);
            a1 = ffma2(ca0.y, vA0.x, a1);
            a2 = ffma2(cb0.x, vA0.y, a2);
            a3 = ffma2(cb0.y, vA0.y, a3);
            b0 = ffma2(ca0.x, vB0.x, b0);
            b1 = ffma2(ca0.y, vB0.x, b1);
            b2 = ffma2(cb0.x, vB0.y, b2);
            b3 = ffma2(cb0.y, vB0.y, b3);
            ca0 = ca1; cb0 = cb1; vA0 = vA1; vB0 = vB1;
            if (jj < 30) { ca1 = can; cb1 = cbn; vA1 = vAn; vB1 = vBn; }
        }
        ull dA0 = fadd2(a0, a2);   // (dot_f0, dot_f1) chain A, output o0
        ull dA1 = fadd2(a1, a3);   // output o0+1
        ull dB0 = fadd2(b0, b2);
        ull dB1 = fadd2(b1, b3);

        const float2 xA = sx[0][t];
        const float2 xB = sx[1][t];
        rA0 = fmaf(xA.x, f2lo(dA0), fmaf(xA.y, f2hi(dA0), rA0));
        rA1 = fmaf(xA.x, f2lo(dA1), fmaf(xA.y, f2hi(dA1), rA1));
        rB0 = fmaf(xB.x, f2lo(dB0), fmaf(xB.y, f2hi(dB0), rB0));
        rB1 = fmaf(xB.x, f2lo(dB1), fmaf(xB.y, f2hi(dB1), rB1));

        *(ulonglong2*)&st[cur ^ 1][0][o0] = make_ulonglong2(dup2(rA0), dup2(rA1));
        *(ulonglong2*)&st[cur ^ 1][1][o0] = make_ulonglong2(dup2(rB0), dup2(rB1));
        __syncwarp();  // all lanes done reading + new state visible

        // End of a pair: release the stage to the producer.
        if ((t & 1) == 1 && lane == 0)
            mbar_arrive(emb[stg]);
    }

    // Final state is in registers.
    float* dst = half ? g_wR : g_vL;
    const int bA = blockIdx.x * 2;
    dst[bA * 64 + o0]           = rA0;
    dst[bA * 64 + o0 + 1]       = rA1;
    dst[(bA + 1) * 64 + o0]     = rB0;
    dst[(bA + 1) * 64 + o0 + 1] = rB1;
}

// ============================================================
// Kernel 3: logits[b][o] = sum_{l,r} vL[l] * oc[o][l][r] * wR[r]
// ============================================================
__global__ void __launch_bounds__(64) combine_kernel(
    const float* __restrict__ oc, float* __restrict__ out)
{
    const int b = blockIdx.x;
    const int tid = threadIdx.x; // 0..63 = r
    __shared__ float vL[64], wR[64];
    __shared__ float red[2];
    vL[tid] = g_vL[b * 64 + tid];
    wR[tid] = g_wR[b * 64 + tid];
    __syncthreads();
    const float w = wR[tid];
    for (int o = 0; o < NOUT; ++o) {
        float acc = 0.f;
        const float* row = oc + (size_t)o * 4096 + tid;
        #pragma unroll 16
        for (int l = 0; l < 64; ++l)
            acc = fmaf(vL[l], row[(size_t)l * 64], acc);
        float pv = acc * w;
        #pragma unroll
        for (int off = 16; off; off >>= 1)
            pv += __shfl_down_sync(0xffffffffu, pv, off);
        if ((tid & 31) == 0) red[tid >> 5] = pv;
        __syncthreads();
        if (tid == 0) out[b * NOUT + o] = red[0] + red[1];
        __syncthreads();
    }
}

extern "C" void kernel_launch(void* const* d_in, const int* in_sizes, int n_in,
                              void* d_out, int out_size) {
    const float* input_data = (const float*)d_in[0]; // [128,256,2]
    const float* cores      = (const float*)d_in[1]; // [256,64,64,2]
    const float* out_core   = (const float*)d_in[2]; // [10,64,64]
    const float* lvec       = (const float*)d_in[3]; // [64]
    const float* rvec       = (const float*)d_in[4]; // [64]
    float* out = (float*)d_out;                      // [128,10]

    cudaFuncSetAttribute(chain_kernel,
                         cudaFuncAttributeMaxDynamicSharedMemorySize,
                         STAGES * PAIR_BYTES);

    // Two no-op launches keep ncu's skip-5 capture on chain_kernel.
    dummy_kernel<<<1, 32>>>();
    dummy_kernel<<<1, 32>>>();
    repack_kernel<<<HALFS, 256>>>(cores);
    chain_kernel<<<dim3(64, 2), 64, STAGES * PAIR_BYTES>>>(input_data, cores, lvec, rvec);
    combine_kernel<<<BATCH, 64>>>(out_core, out);
}

// round 16
// speedup vs baseline: 1.2050x; 1.2050x over previous
#include <cuda_runtime.h>

#define BATCH 128
#define SITES 256
#define BOND 64
#define NOUT 10
#define HALFS 128            // sites per half
#define NPAIRS 64            // site pairs per half
#define SITE_BYTES 32768     // 64*64*2 floats
#define PAIR_BYTES 65536     // 2 sites per TMA stage
#define STAGES 3             // 3 * 64KB ring = 192KB

typedef unsigned long long ull;

// Scratch (device globals — no allocation allowed)
__device__ __align__(16) float g_ct[HALFS * BOND * BOND * 2]; // right half, transposed+reversed
__device__ float g_vL[BATCH * BOND];
__device__ float g_wR[BATCH * BOND];
__device__ unsigned g_flag[64];   // pair-completion flags (odd-count scheme; never reset)

// ---- packed f32x2 helpers ----
static __device__ __forceinline__ ull ffma2(ull a, ull b, ull c) {
    ull d;
    asm("fma.rn.f32x2 %0, %1, %2, %3;" : "=l"(d) : "l"(a), "l"(b), "l"(c));
    return d;
}
static __device__ __forceinline__ ull fadd2(ull a, ull b) {
    ull d;
    asm("add.rn.f32x2 %0, %1, %2;" : "=l"(d) : "l"(a), "l"(b));
    return d;
}
static __device__ __forceinline__ float f2lo(ull v) {
    return __uint_as_float((unsigned)(v & 0xffffffffull));
}
static __device__ __forceinline__ float f2hi(ull v) {
    return __uint_as_float((unsigned)(v >> 32));
}
static __device__ __forceinline__ ull dup2(float v) {
    unsigned u = __float_as_uint(v);
    return ((ull)u << 32) | u;
}
static __device__ __forceinline__ unsigned smem_u32(const void* p) {
    return (unsigned)__cvta_generic_to_shared(p);
}

// ---- mbarrier / bulk-copy primitives ----
static __device__ __forceinline__ void mbar_init(unsigned addr, unsigned count) {
    asm volatile("mbarrier.init.shared.b64 [%0], %1;" :: "r"(addr), "r"(count) : "memory");
}
static __device__ __forceinline__ void mbar_expect_tx(unsigned addr, unsigned bytes) {
    asm volatile("mbarrier.arrive.expect_tx.shared.b64 _, [%0], %1;"
                 :: "r"(addr), "r"(bytes) : "memory");
}
static __device__ __forceinline__ void mbar_arrive(unsigned addr) {
    asm volatile("mbarrier.arrive.shared.b64 _, [%0];" :: "r"(addr) : "memory");
}
static __device__ __forceinline__ void mbar_wait(unsigned addr, unsigned parity) {
    asm volatile(
        "{\n\t"
        ".reg .pred P;\n\t"
        "WAIT_%=:\n\t"
        "mbarrier.try_wait.parity.acquire.cta.shared::cta.b64 P, [%0], %1, 0x989680;\n\t"
        "@P bra.uni DONE_%=;\n\t"
        "bra.uni WAIT_%=;\n\t"
        "DONE_%=:\n\t"
        "}"
        :: "r"(addr), "r"(parity) : "memory");
}
static __device__ __forceinline__ void bulk_g2s(unsigned dst, const void* src,
                                                unsigned bytes, unsigned mbar) {
    asm volatile(
        "cp.async.bulk.shared::cluster.global.mbarrier::complete_tx::bytes [%0], [%1], %2, [%3];"
        :: "r"(dst), "l"(src), "r"(bytes), "r"(mbar) : "memory");
}

// ============================================================
// Kernel 1: repack right-half cores only.
// g_ct[t][r][2l+i] = cores[255 - t][l][r][i]  (transpose, reverse order)
// ============================================================
__global__ void __launch_bounds__(512) repack_kernel(const float* __restrict__ cores) {
    int t = blockIdx.x;            // 0..127
    int s = 255 - t;
    __shared__ float2 sh[64 * 65];
    const float2* src = (const float2*)cores + (size_t)s * 4096; // [l*64 + r] -> (c0,c1)
    float2* dst = (float2*)g_ct + (size_t)t * 4096;              // [r*64 + l]
    for (int idx = threadIdx.x; idx < 4096; idx += blockDim.x) {
        int l = idx >> 6, r = idx & 63;
        sh[r * 65 + l] = src[idx];
    }
    __syncthreads();
    for (int idx = threadIdx.x; idx < 4096; idx += blockDim.x) {
        int r = idx >> 6, l = idx & 63;
        dst[idx] = sh[r * 65 + l];
    }
}

// ============================================================
// Kernel 2: vector chains, COLUMN-split + shfl reduction.
// grid (64,2) x 128 threads = 128 blocks = 128 SMs, 2 chains/block.
// Warp w owns outputs [16w, 16w+16) and computes COMPLETE dots for
// them: lane = slot(0..7) + 8*rp(0..3); lane accumulates rows
// {4jj+rp} for output-pair (2*(8w+slot), +1), both chains. Rows are
// then folded by shfl-butterfly (xor 8, 16) — NO cross-warp partial
// exchange, NO second barrier. State double-buffered in shared as
// interleaved (vA,vA | vB,vB) per row; ONE __syncthreads per site.
// Per-lane register copy of its own outputs feeds the recurrence.
// TMA: private 3-stage x 2-site ring, producer inline on tid 0.
// Epilogue: atomic pair-completion flag; the 2nd-finishing half of
// each batch-pair computes the logits inline (combine fused).
// ============================================================
__global__ void __launch_bounds__(128) chain_kernel(
    const float* __restrict__ x,      // [B][S][2]
    const float* __restrict__ cores,  // [S][l][r][2]
    const float* __restrict__ lvec,
    const float* __restrict__ rvec,
    const float* __restrict__ oc,     // [10][64][64]
    float* __restrict__ out)          // [128][10]
{
    extern __shared__ __align__(128) char dynsmem[];   // STAGES * 64KB
    __shared__ __align__(16) ulonglong2 st2[2][64];    // [buf][row] = (vA,vA | vB,vB)
    __shared__ __align__(16) float2 sx[2][HALFS];      // per-chain x, site order
    __shared__ __align__(8) ull full_store[STAGES];
    __shared__ __align__(8) ull empty_store[STAGES];
    __shared__ float shv[2][64], shw[2][64];
    __shared__ float red[2][2];
    __shared__ unsigned sold;

    const int tid  = threadIdx.x;
    const int w    = tid >> 5;
    const int lane = tid & 31;
    const int slot = lane & 7;
    const int rp   = lane >> 3;
    const int half = blockIdx.y;
    const int bx   = blockIdx.x;
    const int sidx = 8 * w + slot;     // output-pair index 0..31
    const int o0   = 2 * sidx;
    const int o1   = o0 + 1;

    unsigned fmb[STAGES], emb[STAGES];
    #pragma unroll
    for (int si = 0; si < STAGES; ++si) {
        fmb[si] = smem_u32(&full_store[si]);
        emb[si] = smem_u32(&empty_store[si]);
    }
    if (tid == 0) {
        #pragma unroll
        for (int si = 0; si < STAGES; ++si) {
            mbar_init(fmb[si], 1);
            mbar_init(emb[si], 1);
        }
    }

    // Stage per-chain x values (site order t).
    for (int i = tid; i < 2 * HALFS; i += 128) {
        int c = i >> 7, t = i & 127;
        int batch = bx * 2 + c;
        int s = half ? (255 - t) : t;
        sx[c][t] = *(const float2*)(x + ((size_t)batch * SITES + s) * 2);
    }
    // Init state buffer 0 + per-lane register copy of own outputs.
    const float* bv = half ? rvec : lvec;
    if (tid < 64) {
        ull d = dup2(bv[tid]);
        st2[0][tid] = make_ulonglong2(d, d);
    }
    float rA0 = bv[o0], rA1 = bv[o1];
    float rB0 = rA0,    rB1 = rA1;
    __syncthreads();

    const char* gsrc = half ? (const char*)g_ct : (const char*)cores;

    // Prime the ring (pairs 0..2).
    if (tid == 0) {
        #pragma unroll
        for (int pr = 0; pr < STAGES; ++pr) {
            mbar_expect_tx(fmb[pr], PAIR_BYTES);
            bulk_g2s(smem_u32(dynsmem + (size_t)pr * PAIR_BYTES),
                     gsrc + (size_t)pr * PAIR_BYTES, PAIR_BYTES, fmb[pr]);
        }
    }

    // lane's fixed tile offset within a site tile (ull2 units of 16B):
    // row = 4*jj + rp, byte = row*512 + w*128 + slot*16
    const int loff = rp * 32 + w * 8 + slot;

    for (int t = 0; t < HALFS; ++t) {
        const int pair = t >> 1;
        const int stg  = pair % STAGES;

        if ((t & 1) == 0) {
            if (tid == 0 && pair >= 1 && pair + 2 < NPAIRS) {
                const int s2 = (pair + 2) % STAGES;
                mbar_wait(emb[s2], ((pair - 1) / STAGES) & 1);
                mbar_expect_tx(fmb[s2], PAIR_BYTES);
                bulk_g2s(smem_u32(dynsmem + (size_t)s2 * PAIR_BYTES),
                         gsrc + (size_t)(pair + 2) * PAIR_BYTES, PAIR_BYTES, fmb[s2]);
            }
            mbar_wait(fmb[stg], (pair / STAGES) & 1);
        }

        const int cur = t & 1;
        const ulonglong2* tp =
            (const ulonglong2*)(dynsmem + (size_t)stg * PAIR_BYTES + (size_t)cur * SITE_BYTES)
            + loff;
        const ulonglong2* sp = &st2[cur][rp];

        // Complete dot for outputs o0,o1 over rows {4jj+rp}, both chains.
        ull a0 = 0, a1 = 0, b0 = 0, b1 = 0;
        #pragma unroll
        for (int jj = 0; jj < 16; ++jj) {
            ulonglong2 c = tp[jj * 128];   // (c0,c1)[row][o0] | [o1]
            ulonglong2 v = sp[jj * 4];     // (vA,vA | vB,vB)[row]
            a0 = ffma2(c.x, v.x, a0);
            a1 = ffma2(c.y, v.x, a1);
            b0 = ffma2(c.x, v.y, b0);
            b1 = ffma2(c.y, v.y, b1);
        }
        // Fold the 4 row-parities (lanes xor 8, 16) — warp-local.
        a0 = fadd2(a0, __shfl_xor_sync(0xffffffffu, a0, 8));
        a1 = fadd2(a1, __shfl_xor_sync(0xffffffffu, a1, 8));
        b0 = fadd2(b0, __shfl_xor_sync(0xffffffffu, b0, 8));
        b1 = fadd2(b1, __shfl_xor_sync(0xffffffffu, b1, 8));
        a0 = fadd2(a0, __shfl_xor_sync(0xffffffffu, a0, 16));
        a1 = fadd2(a1, __shfl_xor_sync(0xffffffffu, a1, 16));
        b0 = fadd2(b0, __shfl_xor_sync(0xffffffffu, b0, 16));
        b1 = fadd2(b1, __shfl_xor_sync(0xffffffffu, b1, 16));

        if (rp == 0) {
            const float2 xA = sx[0][t];
            const float2 xB = sx[1][t];
            rA0 = fmaf(xA.x, f2lo(a0), fmaf(xA.y, f2hi(a0), rA0));
            rA1 = fmaf(xA.x, f2lo(a1), fmaf(xA.y, f2hi(a1), rA1));
            rB0 = fmaf(xB.x, f2lo(b0), fmaf(xB.y, f2hi(b0), rB0));
            rB1 = fmaf(xB.x, f2lo(b1), fmaf(xB.y, f2hi(b1), rB1));
            const int nxt = cur ^ 1;
            st2[nxt][o0] = make_ulonglong2(dup2(rA0), dup2(rB0));
            st2[nxt][o1] = make_ulonglong2(dup2(rA1), dup2(rB1));
        }

        __syncthreads();  // state visible; all tile reads for this site done

        if ((t & 1) == 1 && tid == 0)
            mbar_arrive(emb[stg]);
    }

    // ---- write final states (registers on rp==0 lanes) ----
    float* dst = half ? g_wR : g_vL;
    if (rp == 0) {
        dst[(bx * 2 + 0) * 64 + o0] = rA0;
        dst[(bx * 2 + 0) * 64 + o1] = rA1;
        dst[(bx * 2 + 1) * 64 + o0] = rB0;
        dst[(bx * 2 + 1) * 64 + o1] = rB1;
    }
    __threadfence();   // release our stores before the flag
    __syncthreads();
    if (tid == 0) sold = atomicAdd(&g_flag[bx], 1u);
    __syncthreads();

    // Second-finishing half of this batch-pair computes the logits.
    if (sold & 1u) {
        __threadfence();  // acquire the other half's stores
        const int bi = tid >> 6;       // which of the 2 batches
        const int r  = tid & 63;
        const int b  = bx * 2 + bi;
        shv[bi][r] = g_vL[b * 64 + r];
        shw[bi][r] = g_wR[b * 64 + r];
        __syncthreads();
        const float wr = shw[bi][r];
        for (int o = 0; o < NOUT; ++o) {
            float acc = 0.f;
            const float* row = oc + (size_t)o * 4096 + r;
            #pragma unroll 16
            for (int l = 0; l < 64; ++l)
                acc = fmaf(shv[bi][l], row[(size_t)l * 64], acc);
            float pv = acc * wr;
            #pragma unroll
            for (int off = 16; off; off >>= 1)
                pv += __shfl_down_sync(0xffffffffu, pv, off);
            if ((r & 31) == 0) red[bi][(r >> 5)] = pv;
            __syncthreads();
            if (r == 0) out[b * NOUT + o] = red[bi][0] + red[bi][1];
            __syncthreads();
        }
    }
}

extern "C" void kernel_launch(void* const* d_in, const int* in_sizes, int n_in,
                              void* d_out, int out_size) {
    const float* input_data = (const float*)d_in[0]; // [128,256,2]
    const float* cores      = (const float*)d_in[1]; // [256,64,64,2]
    const float* out_core   = (const float*)d_in[2]; // [10,64,64]
    const float* lvec       = (const float*)d_in[3]; // [64]
    const float* rvec       = (const float*)d_in[4]; // [64]
    float* out = (float*)d_out;                      // [128,10]

    cudaFuncSetAttribute(chain_kernel,
                         cudaFuncAttributeMaxDynamicSharedMemorySize,
                         STAGES * PAIR_BYTES);

    repack_kernel<<<HALFS, 512>>>(cores);
    chain_kernel<<<dim3(64, 2), 128, STAGES * PAIR_BYTES>>>(
        input_data, cores, lvec, rvec, out_core, out);
}